// round 16
// baseline (speedup 1.0000x reference)
#include <cuda_runtime.h>
#include <cuda_fp16.h>
#include <cstdint>

// ---------------------------------------------------------------------------
// Problem constants
// ---------------------------------------------------------------------------
#define B      4096
#define DIN    1024
#define DOUT   1024
#define NEXP   8
#define BM     128
#define BN     128
#define BK     64              // fp16 elems per k-chunk (128B rows)
#define NCHUNK (DIN / BK)      // 16
#define MAX_TILES 40
#define NSTG   3

#define TILE_B    (BM * 128)           // 16384 bytes per sub-tile (SW128)
#define T_BH      TILE_B
#define STAGE_B   (2 * TILE_B)         // 32768
#define SMEM_ROWS (NSTG * STAGE_B)     // 98304
#define SMEM_BIAS (SMEM_ROWS + 512)
#define SMEM_TOTAL (SMEM_ROWS + 1024)  // 99328 -> 2 blocks/SM

// SW128 XOR swizzle: row r (128B stride), 16B-chunk c in 0..7
#define SWZ(r, c) ((uint32_t)((r) * 128 + ((((c) ^ ((r) & 7))) << 4)))

// Fused-grid layout (all blocks 128 threads)
#define NXB    512    // x convert: 8192 elems (8 rows) per block
#define NWB    1024   // W convert: 8192 elems (8 rows) per block
#define NTAIL  32
#define BID_X     1
#define BID_W     (BID_X + NXB)          // 513
#define BID_TAIL  (BID_W + NWB)          // 1537
#define NPREP     (BID_TAIL + NTAIL)     // 1569
#define NGEMM     (MAX_TILES * 8)        // 320

// ---------------------------------------------------------------------------
// Device-global scratch
// ---------------------------------------------------------------------------
__device__ int g_perm[B];
__device__ int g_tile_expert[MAX_TILES];
__device__ int g_tile_row0[MAX_TILES];
__device__ int g_tile_rows[MAX_TILES];
__device__ int g_ntiles;
__device__ __align__(128) __half g_xh[B * DIN];            // original row order
__device__ __align__(128) __half g_wh[NEXP * DOUT * DIN];
// completion counters: [0]=sort flag, [1]=x blocks, [2+g]=W group g (targets 16)
__device__ unsigned g_cnt[2 + 64];

// ---------------------------------------------------------------------------
// PTX helpers (baseline sm_80+ ISA only)
// ---------------------------------------------------------------------------
__device__ __forceinline__ uint32_t smem_to_u32(const void* p) {
    uint32_t a;
    asm("{ .reg .u64 t; cvta.to.shared.u64 t, %1; cvt.u32.u64 %0, t; }" : "=r"(a) : "l"(p));
    return a;
}
__device__ __forceinline__ void cpasync16(uint32_t dst, const void* src) {
    asm volatile("cp.async.cg.shared.global [%0], [%1], 16;" :: "r"(dst), "l"(src));
}
#define CP_COMMIT() asm volatile("cp.async.commit_group;" ::: "memory")
#define CP_WAIT(n)  asm volatile("cp.async.wait_group %0;" :: "n"(n) : "memory")

__device__ __forceinline__ void ldsm4(uint32_t* r, uint32_t addr) {
    asm volatile("ldmatrix.sync.aligned.m8n8.x4.shared.b16 {%0,%1,%2,%3}, [%4];"
        : "=r"(r[0]), "=r"(r[1]), "=r"(r[2]), "=r"(r[3]) : "r"(addr));
}
__device__ __forceinline__ void mma16816(float* c, const uint32_t* a, uint32_t b0, uint32_t b1) {
    asm volatile(
        "mma.sync.aligned.m16n8k16.row.col.f32.f16.f16.f32 "
        "{%0,%1,%2,%3}, {%4,%5,%6,%7}, {%8,%9}, {%0,%1,%2,%3};"
        : "+f"(c[0]), "+f"(c[1]), "+f"(c[2]), "+f"(c[3])
        : "r"(a[0]), "r"(a[1]), "r"(a[2]), "r"(a[3]), "r"(b0), "r"(b1));
}

// producer epilogue: make this block's global writes visible, then bump counter
__device__ __forceinline__ void arrive(unsigned* ctr) {
    __threadfence();          // every thread fences its own writes (device scope)
    __syncthreads();
    if (threadIdx.x == 0) atomicAdd(ctr, 1u);
}
// consumer: tid0 spins, then fence + block-sync (acquire)
__device__ __forceinline__ void await(const unsigned* ctr, unsigned target) {
    if (threadIdx.x == 0) {
        while (*(volatile const unsigned*)ctr < target) __nanosleep(128);
        __threadfence();
    }
    __syncthreads();
}

// ---------------------------------------------------------------------------
// Sort body (block 0, 128 threads -> 32 elems/thread)
// ---------------------------------------------------------------------------
__device__ void sort_body(const int* __restrict__ actions) {
    __shared__ int cnt[NEXP];
    __shared__ int offs[NEXP + 1];
    __shared__ int cur[NEXP];
    int tid = threadIdx.x;
    int lane = tid & 31;
    if (tid < NEXP) cnt[tid] = 0;
    __syncthreads();
    int ev[32];
#pragma unroll
    for (int q = 0; q < 8; q++) {
        int4 av = ((const int4*)actions)[tid + q * 128];
        ev[q * 4 + 0] = av.x & 7; ev[q * 4 + 1] = av.y & 7;
        ev[q * 4 + 2] = av.z & 7; ev[q * 4 + 3] = av.w & 7;
    }
#pragma unroll
    for (int j = 0; j < 32; j++) {
        unsigned m = __match_any_sync(0xFFFFFFFFu, ev[j]);
        if (lane == (__ffs(m) - 1)) atomicAdd(&cnt[ev[j]], __popc(m));
    }
    __syncthreads();
    if (tid == 0) {
        int s = 0;
        for (int e = 0; e < NEXP; e++) { offs[e] = s; s += cnt[e]; }
        offs[NEXP] = s;
        int nt = 0;
        for (int e = 0; e < NEXP; e++)
            for (int r = offs[e]; r < offs[e + 1]; r += BM) {
                g_tile_expert[nt] = e;
                g_tile_row0[nt]   = r;
                g_tile_rows[nt]   = min(BM, offs[e + 1] - r);
                nt++;
            }
        g_ntiles = nt;
        for (int e = 0; e < NEXP; e++) cur[e] = offs[e];
    }
    __syncthreads();
#pragma unroll
    for (int q = 0; q < 8; q++)
#pragma unroll
        for (int j = 0; j < 4; j++) {
            int i = (tid + q * 128) * 4 + j;
            int e = ev[q * 4 + j];
            unsigned m = __match_any_sync(0xFFFFFFFFu, e);
            int leader = __ffs(m) - 1;
            int rank = __popc(m & ((1u << lane) - 1u));
            int base = 0;
            if (lane == leader) base = atomicAdd(&cur[e], __popc(m));
            base = __shfl_sync(0xFFFFFFFFu, base, leader);
            g_perm[base + rank] = i;
        }
}

// ---------------------------------------------------------------------------
// GEMM body (R15 config: 4 warps, 64x64 warp tiles, K=64 chunks, 3 stages)
// ---------------------------------------------------------------------------
__device__ void gemm_body(int unit, const float* __restrict__ bias,
                          float* __restrict__ out)
{
    const int tid = threadIdx.x;

    await(&g_cnt[0], 1u);                       // sort done
    const int ntiles = __ldcg(&g_ntiles);
    const int t   = unit % MAX_TILES;
    const int n0b = unit / MAX_TILES;
    if (t >= ntiles) return;
    const int e     = __ldcg(&g_tile_expert[t]);
    const int row0  = __ldcg(&g_tile_row0[t]);
    const int nrows = __ldcg(&g_tile_rows[t]);
    const int n0    = n0b * BN;

    extern __shared__ __align__(128) uint8_t smem[];
    const uint32_t sb = smem_to_u32(smem);
    int*   rows_s = (int*)(smem + SMEM_ROWS);
    float* bias_s = (float*)(smem + SMEM_BIAS);

    rows_s[tid] = (tid < nrows) ? __ldcg(&g_perm[row0 + tid]) : -1;
    bias_s[tid] = bias[e * DOUT + n0 + tid];

    // wait for x (all) + our W row-group, then acquire
    if (tid == 0) {
        while (*(volatile unsigned*)&g_cnt[1] < NXB) __nanosleep(128);
        while (*(volatile unsigned*)&g_cnt[2 + e * 8 + n0b] < 16u) __nanosleep(128);
        __threadfence();
    }
    __syncthreads();   // also covers rows_s/bias_s visibility

    const int wid  = tid >> 5;
    const int lane = tid & 31;
    const int wm   = wid & 1;
    const int wn   = wid >> 1;

    // Loader: 8 chunks of 16B per thread per sub-tile
    const int cq  = tid & 7;
    const int r0q = tid >> 3;
    uint32_t xoff[8];
#pragma unroll
    for (int q = 0; q < 8; q++) {
        int gr = rows_s[r0q + 16 * q]; if (gr < 0) gr = 0;
        xoff[q] = (uint32_t)(gr * DIN + cq * 8);
    }
    const size_t   wo0  = (size_t)(e * DOUT + n0 + r0q) * DIN + cq * 8;
    const uint32_t dsw0 = SWZ(r0q, cq);

#define LOAD_CHUNK(ch, stg) do {                                            \
        int k0_ = (ch) * BK;                                                \
        uint32_t sB_ = sb + (stg) * STAGE_B;                                \
        _Pragma("unroll")                                                   \
        for (int q = 0; q < 8; q++) {                                       \
            uint32_t dq = dsw0 + q * 2048;                                  \
            cpasync16(sB_ + dq,        g_xh + xoff[q] + k0_);               \
            cpasync16(sB_ + T_BH + dq, g_wh + wo0 + (size_t)q * 16 * DIN + k0_); \
        }                                                                   \
        CP_COMMIT();                                                        \
    } while (0)

    float acc[4][8][4];
#pragma unroll
    for (int i = 0; i < 4; i++)
#pragma unroll
        for (int j = 0; j < 8; j++)
#pragma unroll
            for (int k = 0; k < 4; k++) acc[i][j][k] = 0.0f;

    uint32_t aoff[4], boff[4];
#pragma unroll
    for (int mt = 0; mt < 4; mt++) {
        int r = wm * 64 + mt * 16 + (lane & 15);
        aoff[mt] = SWZ(r, (lane >> 4));
    }
#pragma unroll
    for (int np = 0; np < 4; np++) {
        int nr = wn * 64 + np * 16 + (lane & 7) + ((lane >> 4) << 3);
        boff[np] = SWZ(nr, ((lane >> 3) & 1));
    }

    LOAD_CHUNK(0, 0);
    LOAD_CHUNK(1, 1);
    for (int ch = 0; ch < NCHUNK; ch++) {
        int stg = ch % NSTG;
        if (ch < NCHUNK - 1) { CP_WAIT(1); } else { CP_WAIT(0); }
        __syncthreads();

        uint32_t s0 = sb + stg * STAGE_B;
#pragma unroll
        for (int ks = 0; ks < 4; ks++) {
            const uint32_t kx = (uint32_t)ks << 5;
            uint32_t ah[4][4], bb[4][4];
#pragma unroll
            for (int mt = 0; mt < 4; mt++)
                ldsm4(ah[mt], s0 + (aoff[mt] ^ kx));
#pragma unroll
            for (int np = 0; np < 4; np++)
                ldsm4(bb[np], s0 + T_BH + (boff[np] ^ kx));
#pragma unroll
            for (int mt = 0; mt < 4; mt++)
#pragma unroll
                for (int np = 0; np < 4; np++) {
                    mma16816(acc[mt][np * 2],     ah[mt], bb[np][0], bb[np][1]);
                    mma16816(acc[mt][np * 2 + 1], ah[mt], bb[np][2], bb[np][3]);
                }
        }
        if (ch + 2 < NCHUNK) LOAD_CHUNK(ch + 2, (ch + 2) % NSTG);
    }

    // Epilogue: scatter with bias
#pragma unroll
    for (int mt = 0; mt < 4; mt++) {
        int rbase = wm * 64 + mt * 16 + (lane >> 2);
#pragma unroll
        for (int half = 0; half < 2; half++) {
            int gr = rows_s[rbase + half * 8];
            if (gr < 0) continue;
            float* orow = out + (size_t)gr * DOUT + n0;
#pragma unroll
            for (int nt = 0; nt < 8; nt++) {
                int col = wn * 64 + nt * 8 + (lane & 3) * 2;
                float2 v;
                v.x = acc[mt][nt][half * 2 + 0] + bias_s[col];
                v.y = acc[mt][nt][half * 2 + 1] + bias_s[col + 1];
                *(float2*)(orow + col) = v;
            }
        }
    }
#undef LOAD_CHUNK
}

// ---------------------------------------------------------------------------
// Fused mega-kernel: [0]=sort, [1,513)=x conv, [513,1537)=W conv,
// [1537,1569)=tail, [1569,1889)=gemm units (spin on data-ready counters).
// ---------------------------------------------------------------------------
__global__ __launch_bounds__(128, 2) void mega_kernel(
    const float* __restrict__ W, const float* __restrict__ xs,
    const int* __restrict__ mxs, const int* __restrict__ actions,
    const float* __restrict__ bias, float* __restrict__ out, int extra)
{
    const int bid = blockIdx.x;
    const int tid = threadIdx.x;

    if (bid == 0) {
        sort_body(actions);
        arrive(&g_cnt[0]);
    } else if (bid < BID_W) {
        size_t base = (size_t)(bid - BID_X) * 8192;
#pragma unroll
        for (int j = 0; j < 16; j++) {
            size_t i = base + (size_t)(tid + j * 128) * 4;
            float4 v = *(const float4*)(xs + i);
            *(__half2*)(g_xh + i)     = __half2(__float2half(v.x), __float2half(v.y));
            *(__half2*)(g_xh + i + 2) = __half2(__float2half(v.z), __float2half(v.w));
        }
        arrive(&g_cnt[1]);
    } else if (bid < BID_TAIL) {
        int q = bid - BID_W;
        size_t base = (size_t)q * 8192;
#pragma unroll
        for (int j = 0; j < 16; j++) {
            size_t i = base + (size_t)(tid + j * 128) * 4;
            float4 v = *(const float4*)(W + i);
            *(__half2*)(g_wh + i)     = __half2(__float2half(v.x), __float2half(v.y));
            *(__half2*)(g_wh + i + 2) = __half2(__float2half(v.z), __float2half(v.w));
        }
        arrive(&g_cnt[2 + (q >> 4)]);   // rows q*8..q*8+7 -> group (q*8)>>7
    } else if (bid < NPREP) {
        int i = (bid - BID_TAIL) * 128 + tid;
        if (i < B && extra > 0) {
            const size_t base = (size_t)B * DOUT;
            if (extra >= B)     out[base + i]     = (float)mxs[i];
            if (extra >= 2 * B) out[base + B + i] = (float)actions[i];
        }
    } else {
        gemm_body(bid - NPREP, bias, out);
    }
}

// ---------------------------------------------------------------------------
// Host launch
// ---------------------------------------------------------------------------
extern "C" void kernel_launch(void* const* d_in, const int* in_sizes, int n_in,
                              void* d_out, int out_size)
{
    const float* xs      = (const float*)d_in[0];
    const int*   mxs     = (const int*)d_in[1];
    const int*   actions = (const int*)d_in[2];
    const float* W       = (const float*)d_in[3];
    const float* bias    = (const float*)d_in[4];
    float*       out     = (float*)d_out;

    static bool attr_done = false;
    if (!attr_done) {
        cudaFuncSetAttribute(mega_kernel, cudaFuncAttributeMaxDynamicSharedMemorySize, SMEM_TOTAL);
        attr_done = true;
    }

    void* cntp = nullptr;
    cudaGetSymbolAddress(&cntp, g_cnt);
    cudaMemsetAsync(cntp, 0, sizeof(unsigned) * (2 + 64));

    int extra = out_size - B * DOUT;
    mega_kernel<<<NPREP + NGEMM, 128, SMEM_TOTAL>>>(W, xs, mxs, actions, bias, out, extra);
}

// round 17
// speedup vs baseline: 1.5729x; 1.5729x over previous
#include <cuda_runtime.h>
#include <cuda_fp16.h>
#include <cstdint>

// ---------------------------------------------------------------------------
// Problem constants
// ---------------------------------------------------------------------------
#define B      4096
#define DIN    1024
#define DOUT   1024
#define NEXP   8
#define BM     128
#define BN     128
#define BK     64              // fp16 elems per k-chunk (128B rows)
#define NCHUNK (DIN / BK)      // 16
#define MAX_TILES 40
#define NSTG   3

#define TILE_B    (BM * 128)           // 16384 bytes per sub-tile (SW128)
#define T_BH      TILE_B
#define STAGE_B   (2 * TILE_B)         // 32768
#define SMEM_ROWS (NSTG * STAGE_B)     // 98304
#define SMEM_BIAS (SMEM_ROWS + 512)
#define SMEM_TOTAL (SMEM_ROWS + 1024)  // 99328 -> 2 CTAs/SM

// SW128 XOR swizzle: row r (128B stride), 16B-chunk c in 0..7
#define SWZ(r, c) ((uint32_t)((r) * 128 + ((((c) ^ ((r) & 7))) << 4)))

// ---------------------------------------------------------------------------
// Device-global scratch
// ---------------------------------------------------------------------------
__device__ int g_perm[B];
__device__ int g_tile_expert[MAX_TILES];
__device__ int g_tile_row0[MAX_TILES];
__device__ int g_tile_rows[MAX_TILES];
__device__ int g_ntiles;
__device__ __align__(128) __half g_xh[B * DIN];            // original row order
__device__ __align__(128) __half g_wh[NEXP * DOUT * DIN];

// ---------------------------------------------------------------------------
// PTX helpers (baseline sm_80+ ISA only)
// ---------------------------------------------------------------------------
__device__ __forceinline__ uint32_t smem_to_u32(const void* p) {
    uint32_t a;
    asm("{ .reg .u64 t; cvta.to.shared.u64 t, %1; cvt.u32.u64 %0, t; }" : "=r"(a) : "l"(p));
    return a;
}
__device__ __forceinline__ void cpasync16(uint32_t dst, const void* src) {
    asm volatile("cp.async.cg.shared.global [%0], [%1], 16;" :: "r"(dst), "l"(src));
}
#define CP_COMMIT() asm volatile("cp.async.commit_group;" ::: "memory")
#define CP_WAIT(n)  asm volatile("cp.async.wait_group %0;" :: "n"(n) : "memory")

__device__ __forceinline__ void ldsm4(uint32_t* r, uint32_t addr) {
    asm volatile("ldmatrix.sync.aligned.m8n8.x4.shared.b16 {%0,%1,%2,%3}, [%4];"
        : "=r"(r[0]), "=r"(r[1]), "=r"(r[2]), "=r"(r[3]) : "r"(addr));
}
__device__ __forceinline__ void mma16816(float* c, const uint32_t* a, uint32_t b0, uint32_t b1) {
    asm volatile(
        "mma.sync.aligned.m16n8k16.row.col.f32.f16.f16.f32 "
        "{%0,%1,%2,%3}, {%4,%5,%6,%7}, {%8,%9}, {%0,%1,%2,%3};"
        : "+f"(c[0]), "+f"(c[1]), "+f"(c[2]), "+f"(c[3])
        : "r"(a[0]), "r"(a[1]), "r"(a[2]), "r"(a[3]), "r"(b0), "r"(b1));
}

// ---------------------------------------------------------------------------
// Sort body (runs as block 0 of prep grid, blockDim 256 -> 16 elems/thread)
// ---------------------------------------------------------------------------
__device__ void sort_body(const int* __restrict__ actions) {
    __shared__ int cnt[NEXP];
    __shared__ int offs[NEXP + 1];
    __shared__ int cur[NEXP];
    int tid = threadIdx.x;
    int lane = tid & 31;
    if (tid < NEXP) cnt[tid] = 0;
    __syncthreads();
    int4 av[4];
    int ev[16];
#pragma unroll
    for (int q = 0; q < 4; q++) {
        av[q] = ((const int4*)actions)[tid + q * 256];
        ev[q * 4 + 0] = av[q].x & 7; ev[q * 4 + 1] = av[q].y & 7;
        ev[q * 4 + 2] = av[q].z & 7; ev[q * 4 + 3] = av[q].w & 7;
    }
#pragma unroll
    for (int j = 0; j < 16; j++) {
        unsigned m = __match_any_sync(0xFFFFFFFFu, ev[j]);
        if (lane == (__ffs(m) - 1)) atomicAdd(&cnt[ev[j]], __popc(m));
    }
    __syncthreads();
    if (tid == 0) {
        int s = 0;
        for (int e = 0; e < NEXP; e++) { offs[e] = s; s += cnt[e]; }
        offs[NEXP] = s;
        int nt = 0;
        for (int e = 0; e < NEXP; e++)
            for (int r = offs[e]; r < offs[e + 1]; r += BM) {
                g_tile_expert[nt] = e;
                g_tile_row0[nt]   = r;
                g_tile_rows[nt]   = min(BM, offs[e + 1] - r);
                nt++;
            }
        g_ntiles = nt;
        for (int e = 0; e < NEXP; e++) cur[e] = offs[e];
    }
    __syncthreads();
#pragma unroll
    for (int q = 0; q < 4; q++)
#pragma unroll
        for (int j = 0; j < 4; j++) {
            int i = (tid + q * 256) * 4 + j;
            int e = ev[q * 4 + j];
            unsigned m = __match_any_sync(0xFFFFFFFFu, e);
            int leader = __ffs(m) - 1;
            int rank = __popc(m & ((1u << lane) - 1u));
            int base = 0;
            if (lane == leader) base = atomicAdd(&cur[e], __popc(m));
            base = __shfl_sync(0xFFFFFFFFu, base, leader);
            g_perm[base + rank] = i;
        }
}

// ---------------------------------------------------------------------------
// Prep kernel (256 threads/block): block 0 = sort;
// [1, 1+NWBLK)          : W -> fp16, 16 elems/thread (streaming loads)
// [1+NWBLK, +NXBLK)     : x -> fp16, 16 elems/thread
// last 16               : passthrough tail
// ---------------------------------------------------------------------------
#define NWBLK 2048   // 8M elems / (256 thr * 16)
#define NXBLK 1024   // 4M elems / (256 thr * 16)
__global__ void prep_kernel(const float* __restrict__ W, const float* __restrict__ xs,
                            const int* __restrict__ mxs, const int* __restrict__ actions,
                            float* __restrict__ out, int extra) {
    if (blockIdx.x == 0) {
        sort_body(actions);
        return;
    }
    int bid = blockIdx.x - 1;
    if (bid < NWBLK) {
        size_t base = (size_t)bid * 4096;
#pragma unroll
        for (int j = 0; j < 4; j++) {
            size_t i = base + (size_t)(threadIdx.x + j * 256) * 4;
            float4 v = __ldcs((const float4*)(W + i));
            *(__half2*)(g_wh + i)     = __half2(__float2half(v.x), __float2half(v.y));
            *(__half2*)(g_wh + i + 2) = __half2(__float2half(v.z), __float2half(v.w));
        }
    } else if (bid < NWBLK + NXBLK) {
        size_t base = (size_t)(bid - NWBLK) * 4096;
#pragma unroll
        for (int j = 0; j < 4; j++) {
            size_t i = base + (size_t)(threadIdx.x + j * 256) * 4;
            float4 v = __ldcs((const float4*)(xs + i));
            *(__half2*)(g_xh + i)     = __half2(__float2half(v.x), __float2half(v.y));
            *(__half2*)(g_xh + i + 2) = __half2(__float2half(v.z), __float2half(v.w));
        }
    } else {
        int i = (bid - NWBLK - NXBLK) * 256 + threadIdx.x;
        if (i < B && extra > 0) {
            const size_t base = (size_t)B * DOUT;
            if (extra >= B)     out[base + i]     = (float)mxs[i];
            if (extra >= 2 * B) out[base + B + i] = (float)actions[i];
        }
    }
}

// ---------------------------------------------------------------------------
// GEMM (R15 config): fp16 mma.sync, K=64 chunks, SW128 swizzle, 3-stage
// cp.async. 128 threads = 4 warps, each owning a 64x64 warp tile:
//   wm = wid&1 (row half), wn = wid>>1 (col half).
// ---------------------------------------------------------------------------
__global__ __launch_bounds__(128, 2) void gemm_mma(
    const float* __restrict__ bias,
    float* __restrict__ out)
{
    int t = blockIdx.x;
    if (t >= g_ntiles) return;
    const int e     = g_tile_expert[t];
    const int row0  = g_tile_row0[t];
    const int nrows = g_tile_rows[t];
    const int n0    = blockIdx.y * BN;

    extern __shared__ __align__(128) uint8_t smem[];
    const uint32_t sb = smem_to_u32(smem);
    int*   rows_s = (int*)(smem + SMEM_ROWS);
    float* bias_s = (float*)(smem + SMEM_BIAS);

    const int tid  = threadIdx.x;
    const int wid  = tid >> 5;
    const int lane = tid & 31;
    const int wm   = wid & 1;
    const int wn   = wid >> 1;

    rows_s[tid] = (tid < nrows) ? g_perm[row0 + tid] : -1;
    bias_s[tid] = bias[e * DOUT + n0 + tid];
    __syncthreads();   // loaders read rows_s below

    // Loader: 8 chunks of 16B per thread per sub-tile.
    const int cq  = tid & 7;
    const int r0q = tid >> 3;
    uint32_t xoff[8];
#pragma unroll
    for (int q = 0; q < 8; q++) {
        int gr = rows_s[r0q + 16 * q]; if (gr < 0) gr = 0;
        xoff[q] = (uint32_t)(gr * DIN + cq * 8);
    }
    const size_t   wo0  = (size_t)(e * DOUT + n0 + r0q) * DIN + cq * 8;
    const uint32_t dsw0 = SWZ(r0q, cq);

#define LOAD_CHUNK(ch, stg) do {                                            \
        int k0_ = (ch) * BK;                                                \
        uint32_t sB_ = sb + (stg) * STAGE_B;                                \
        _Pragma("unroll")                                                   \
        for (int q = 0; q < 8; q++) {                                       \
            uint32_t dq = dsw0 + q * 2048;                                  \
            cpasync16(sB_ + dq,        g_xh + xoff[q] + k0_);               \
            cpasync16(sB_ + T_BH + dq, g_wh + wo0 + (size_t)q * 16 * DIN + k0_); \
        }                                                                   \
        CP_COMMIT();                                                        \
    } while (0)

    float acc[4][8][4];
#pragma unroll
    for (int i = 0; i < 4; i++)
#pragma unroll
        for (int j = 0; j < 8; j++)
#pragma unroll
            for (int k = 0; k < 4; k++) acc[i][j][k] = 0.0f;

    // ldmatrix base offsets (ks=0); k-step applies ^ (ks<<5)
    uint32_t aoff[4], boff[4];
#pragma unroll
    for (int mt = 0; mt < 4; mt++) {
        int r = wm * 64 + mt * 16 + (lane & 15);
        aoff[mt] = SWZ(r, (lane >> 4));
    }
#pragma unroll
    for (int np = 0; np < 4; np++) {
        int nr = wn * 64 + np * 16 + (lane & 7) + ((lane >> 4) << 3);
        boff[np] = SWZ(nr, ((lane >> 3) & 1));
    }

    LOAD_CHUNK(0, 0);
    LOAD_CHUNK(1, 1);
    for (int ch = 0; ch < NCHUNK; ch++) {
        int stg = ch % NSTG;
        if (ch < NCHUNK - 1) { CP_WAIT(1); } else { CP_WAIT(0); }
        __syncthreads();

        uint32_t s0 = sb + stg * STAGE_B;
#pragma unroll
        for (int ks = 0; ks < 4; ks++) {
            const uint32_t kx = (uint32_t)ks << 5;
            uint32_t ah[4][4], bb[4][4];
#pragma unroll
            for (int mt = 0; mt < 4; mt++)
                ldsm4(ah[mt], s0 + (aoff[mt] ^ kx));
#pragma unroll
            for (int np = 0; np < 4; np++)
                ldsm4(bb[np], s0 + T_BH + (boff[np] ^ kx));
#pragma unroll
            for (int mt = 0; mt < 4; mt++)
#pragma unroll
                for (int np = 0; np < 4; np++) {
                    mma16816(acc[mt][np * 2],     ah[mt], bb[np][0], bb[np][1]);
                    mma16816(acc[mt][np * 2 + 1], ah[mt], bb[np][2], bb[np][3]);
                }
        }
        // prefetch chunk ch+2 into slot (ch+2)%3 (consumed in iter ch-1)
        if (ch + 2 < NCHUNK) LOAD_CHUNK(ch + 2, (ch + 2) % NSTG);
    }

    // Epilogue: scatter with bias (warp covers rows wm*64..+63, cols wn*64..+63)
#pragma unroll
    for (int mt = 0; mt < 4; mt++) {
        int rbase = wm * 64 + mt * 16 + (lane >> 2);
#pragma unroll
        for (int half = 0; half < 2; half++) {
            int gr = rows_s[rbase + half * 8];
            if (gr < 0) continue;
            float* orow = out + (size_t)gr * DOUT + n0;
#pragma unroll
            for (int nt = 0; nt < 8; nt++) {
                int col = wn * 64 + nt * 8 + (lane & 3) * 2;
                float2 v;
                v.x = acc[mt][nt][half * 2 + 0] + bias_s[col];
                v.y = acc[mt][nt][half * 2 + 1] + bias_s[col + 1];
                *(float2*)(orow + col) = v;
            }
        }
    }
#undef LOAD_CHUNK
}

// ---------------------------------------------------------------------------
// Host launch
// ---------------------------------------------------------------------------
extern "C" void kernel_launch(void* const* d_in, const int* in_sizes, int n_in,
                              void* d_out, int out_size)
{
    const float* xs      = (const float*)d_in[0];
    const int*   mxs     = (const int*)d_in[1];
    const int*   actions = (const int*)d_in[2];
    const float* W       = (const float*)d_in[3];
    const float* bias    = (const float*)d_in[4];
    float*       out     = (float*)d_out;

    static bool attr_done = false;
    if (!attr_done) {
        cudaFuncSetAttribute(gemm_mma, cudaFuncAttributeMaxDynamicSharedMemorySize, SMEM_TOTAL);
        attr_done = true;
    }

    int extra = out_size - B * DOUT;

    prep_kernel<<<1 + NWBLK + NXBLK + 16, 256>>>(W, xs, mxs, actions, out, extra);

    dim3 grid(MAX_TILES, DOUT / BN);
    gemm_mma<<<grid, 128, SMEM_TOTAL>>>(bias, out);
}